// round 1
// baseline (speedup 1.0000x reference)
#include <cuda_runtime.h>
#include <math.h>

// Problem constants
#define NT 8192        // N tokens
#define DD 1024        // embedding dim
#define ITERS 20
#define CSPLIT 128     // row-chunks for column LSE

// ---------------- scratch (device globals; no runtime alloc) ----------------
__device__ float g_h[(size_t)NT * DD];   // hidden buffer
__device__ float g_a[(size_t)NT * DD];   // proj(emb_a)
__device__ float g_b[(size_t)NT * DD];   // proj(emb_b)
__device__ float g_r[NT];
__device__ float g_c[NT];
__device__ float2 g_part[(size_t)CSPLIT * NT];

// ---------------- SGEMM: 128x128 tile, BK=16, 8x8 per thread ----------------
#define BM 128
#define BN 128
#define BK 16
#define TM 8
#define TN 8

enum { EPI_GELU = 0, EPI_BIAS = 1, EPI_SCALE = 2 };

template <int EPI, bool B_TRANS>
__global__ void __launch_bounds__(256)
sgemm_kernel(const float* __restrict__ A, const float* __restrict__ B,
             const float* __restrict__ bias, float* __restrict__ C,
             int M, int N, int K)
{
    __shared__ float As[BK][BM];
    __shared__ float Bs[BK][BN];

    const int tid = threadIdx.x;
    const int bm = blockIdx.y * BM;
    const int bn = blockIdx.x * BN;

    const int tx = tid % 16;  // col group
    const int ty = tid / 16;  // row group

    // A-tile loader: 128 rows x 16 cols via float4, two passes of 64 rows
    const int a_row = tid / 4;            // 0..63
    const int a_col = (tid % 4) * 4;      // 0,4,8,12
    // B-tile loader (NN): 16 rows x 128 cols via float4, two passes of 8 rows
    const int b_row = tid / 32;           // 0..7
    const int b_col = (tid % 32) * 4;

    float acc[TM][TN] = {};

    for (int k0 = 0; k0 < K; k0 += BK) {
#pragma unroll
        for (int r = 0; r < 2; r++) {
            int row = a_row + r * 64;
            float4 v = *(const float4*)(A + (size_t)(bm + row) * K + k0 + a_col);
            As[a_col + 0][row] = v.x;
            As[a_col + 1][row] = v.y;
            As[a_col + 2][row] = v.z;
            As[a_col + 3][row] = v.w;
        }
        if (B_TRANS) {
            // C_ij = sum_k A_ik * B_jk ; B is [N,K] row-major
#pragma unroll
            for (int r = 0; r < 2; r++) {
                int row = a_row + r * 64;
                float4 v = *(const float4*)(B + (size_t)(bn + row) * K + k0 + a_col);
                Bs[a_col + 0][row] = v.x;
                Bs[a_col + 1][row] = v.y;
                Bs[a_col + 2][row] = v.z;
                Bs[a_col + 3][row] = v.w;
            }
        } else {
#pragma unroll
            for (int r = 0; r < 2; r++) {
                int row = b_row + r * 8;
                float4 v = *(const float4*)(B + (size_t)(k0 + row) * N + bn + b_col);
                *(float4*)&Bs[row][b_col] = v;
            }
        }
        __syncthreads();

#pragma unroll
        for (int kk = 0; kk < BK; kk++) {
            float a[TM], b[TN];
#pragma unroll
            for (int i = 0; i < TM; i++) a[i] = As[kk][ty * TM + i];
#pragma unroll
            for (int j = 0; j < TN; j++) b[j] = Bs[kk][tx * TN + j];
#pragma unroll
            for (int i = 0; i < TM; i++)
#pragma unroll
                for (int j = 0; j < TN; j++)
                    acc[i][j] = fmaf(a[i], b[j], acc[i][j]);
        }
        __syncthreads();
    }

#pragma unroll
    for (int i = 0; i < TM; i++) {
        int row = bm + ty * TM + i;
#pragma unroll
        for (int j = 0; j < TN; j++) {
            int col = bn + tx * TN + j;
            float v = acc[i][j];
            if (EPI == EPI_GELU) {
                v += bias[col];
                v = 0.5f * v * (1.0f + erff(v * 0.70710678118654752f));
            } else if (EPI == EPI_BIAS) {
                v += bias[col];
            } else {
                v *= 20.0f;  // 1/TEMP
            }
            C[(size_t)row * N + col] = v;
        }
    }
}

// ---------------- online LSE helpers ----------------
__device__ __forceinline__ void lse_upd(float& m, float& l, float v)
{
    if (v <= m) {
        l += __expf(v - m);
    } else {
        l = l * __expf(m - v) + 1.0f;
        m = v;
    }
}

__global__ void zero_c_kernel(float* __restrict__ c)
{
    int j = blockIdx.x * blockDim.x + threadIdx.x;
    if (j < NT) c[j] = 0.0f;
}

// r_i = LSE_j(s_ij - c_j); one block per row
__global__ void __launch_bounds__(256)
row_lse_kernel(const float* __restrict__ S, const float* __restrict__ c,
               float* __restrict__ r)
{
    const int row = blockIdx.x;
    const int tid = threadIdx.x;
    const float4* s4 = (const float4*)(S + (size_t)row * NT);
    const float4* c4 = (const float4*)c;

    float m = -INFINITY, l = 0.0f;
    for (int j = tid; j < NT / 4; j += 256) {
        float4 s = s4[j];
        float4 cc = c4[j];
        lse_upd(m, l, s.x - cc.x);
        lse_upd(m, l, s.y - cc.y);
        lse_upd(m, l, s.z - cc.z);
        lse_upd(m, l, s.w - cc.w);
    }

    __shared__ float sm[256], sl[256];
    sm[tid] = m; sl[tid] = l;
    __syncthreads();
    for (int s = 128; s > 0; s >>= 1) {
        if (tid < s) {
            float m2 = sm[tid + s], l2 = sl[tid + s];
            float nm = fmaxf(sm[tid], m2);
            sl[tid] = sl[tid] * __expf(sm[tid] - nm) + l2 * __expf(m2 - nm);
            sm[tid] = nm;
        }
        __syncthreads();
    }
    if (tid == 0) r[row] = sm[0] + __logf(sl[0]);
}

// partial c_j over a row-chunk; each thread owns 4 columns (float4 coalesced)
__global__ void __launch_bounds__(256)
col_lse_partial_kernel(const float* __restrict__ S, const float* __restrict__ r,
                       float2* __restrict__ part)
{
    const int j4 = blockIdx.x * blockDim.x + threadIdx.x;  // float4 column idx
    const int chunk = blockIdx.y;
    const int rowsPer = NT / CSPLIT;
    const int i0 = chunk * rowsPer;

    float m0 = -INFINITY, m1 = -INFINITY, m2 = -INFINITY, m3 = -INFINITY;
    float l0 = 0.f, l1 = 0.f, l2 = 0.f, l3 = 0.f;

    const float4* S4 = (const float4*)S;
    for (int i = i0; i < i0 + rowsPer; i++) {
        float4 s = S4[(size_t)i * (NT / 4) + j4];
        float rv = __ldg(&r[i]);
        lse_upd(m0, l0, s.x - rv);
        lse_upd(m1, l1, s.y - rv);
        lse_upd(m2, l2, s.z - rv);
        lse_upd(m3, l3, s.w - rv);
    }
    int j = j4 * 4;
    float2* p = part + (size_t)chunk * NT + j;
    p[0] = make_float2(m0, l0);
    p[1] = make_float2(m1, l1);
    p[2] = make_float2(m2, l2);
    p[3] = make_float2(m3, l3);
}

__global__ void __launch_bounds__(256)
col_lse_combine_kernel(const float2* __restrict__ part, float* __restrict__ c)
{
    const int j = blockIdx.x * blockDim.x + threadIdx.x;
    float m = -INFINITY, l = 0.0f;
    for (int k = 0; k < CSPLIT; k++) {
        float2 p = part[(size_t)k * NT + j];
        float nm = fmaxf(m, p.x);
        l = l * __expf(m - nm) + p.y * __expf(p.x - nm);
        m = nm;
    }
    c[j] = m + __logf(l);
}

// out = exp(s - r_i - c_j), in place
__global__ void __launch_bounds__(256)
final_exp_kernel(float* __restrict__ S, const float* __restrict__ r,
                 const float* __restrict__ c)
{
    size_t idx = (size_t)blockIdx.x * blockDim.x + threadIdx.x;  // float4 idx
    int row = (int)(idx >> 11);          // 2048 float4 per row
    int j4 = (int)(idx & 2047);
    float4 s = ((const float4*)S)[idx];
    float rv = r[row];
    float4 cc = ((const float4*)c)[j4];
    s.x = __expf(s.x - rv - cc.x);
    s.y = __expf(s.y - rv - cc.y);
    s.z = __expf(s.z - rv - cc.z);
    s.w = __expf(s.w - rv - cc.w);
    ((float4*)S)[idx] = s;
}

// ---------------- launch ----------------
extern "C" void kernel_launch(void* const* d_in, const int* in_sizes, int n_in,
                              void* d_out, int out_size)
{
    const float* emb_a = (const float*)d_in[0];
    const float* emb_b = (const float*)d_in[1];
    const float* W1    = (const float*)d_in[2];
    const float* b1    = (const float*)d_in[3];
    const float* W2    = (const float*)d_in[4];
    const float* b2    = (const float*)d_in[5];
    float* out = (float*)d_out;

    float *h, *a, *b, *r, *c;
    float2* part;
    cudaGetSymbolAddress((void**)&h, g_h);
    cudaGetSymbolAddress((void**)&a, g_a);
    cudaGetSymbolAddress((void**)&b, g_b);
    cudaGetSymbolAddress((void**)&r, g_r);
    cudaGetSymbolAddress((void**)&c, g_c);
    cudaGetSymbolAddress((void**)&part, g_part);

    dim3 blk(256);
    dim3 grid_mlp(DD / BN, NT / BM);   // (8, 64)
    dim3 grid_big(NT / BN, NT / BM);   // (64, 64)

    // proj(emb_a)
    sgemm_kernel<EPI_GELU, false><<<grid_mlp, blk>>>(emb_a, W1, b1, h, NT, DD, DD);
    sgemm_kernel<EPI_BIAS, false><<<grid_mlp, blk>>>(h, W2, b2, a, NT, DD, DD);
    // proj(emb_b)
    sgemm_kernel<EPI_GELU, false><<<grid_mlp, blk>>>(emb_b, W1, b1, h, NT, DD, DD);
    sgemm_kernel<EPI_BIAS, false><<<grid_mlp, blk>>>(h, W2, b2, b, NT, DD, DD);
    // scores = (a @ b^T) / TEMP  -> d_out
    sgemm_kernel<EPI_SCALE, true><<<grid_big, blk>>>(a, b, nullptr, out, NT, NT, DD);

    // Sinkhorn in (r, c) potential form: matrix stays read-only
    zero_c_kernel<<<NT / 256, blk>>>(c);
    for (int it = 0; it < ITERS; it++) {
        row_lse_kernel<<<NT, blk>>>(out, c, r);
        col_lse_partial_kernel<<<dim3((NT / 4) / 256, CSPLIT), blk>>>(out, r, part);
        col_lse_combine_kernel<<<NT / 256, blk>>>(part, c);
    }

    final_exp_kernel<<<(NT / 4) * (NT / 256), blk>>>(out, r, c);
}